// round 10
// baseline (speedup 1.0000x reference)
#include <cuda_runtime.h>
#include <cuda_bf16.h>
#include <math.h>
#include <stdint.h>

#define V     8192
#define NREF  262144
#define NALT  131072
#define FREAD 11
#define FINFO 9
#define H     256
#define MAX_ALT 10

#define TILE_R 64

// ---------------- scratch ----------------
__device__ float g_ref_sums[V * H];
__device__ float g_alt_sums[V * H];
__device__ int   g_ref_cnt[V];
__device__ int   g_alt_cnt[V];
// weights, interleaved mma fragments: uint4 {hi_r0, hi_r1, lo_r0, lo_r1} per [kt][nt(32)][lane(32)]
__device__ __align__(16) uint4 g_W1i[16 * 1024];
__device__ __align__(16) uint4 g_r0i[48 * 1024];
__device__ __align__(16) uint4 g_r1i[16 * 1024];
__device__ __align__(16) uint4 g_oWi[48 * 1024];

// ---------------- helpers ----------------
__device__ __forceinline__ float lrelu(float x) { return x > 0.f ? x : 0.01f * x; }
__device__ __forceinline__ float sigmoidf_(float x) { return 1.f / (1.f + __expf(-x)); }

__device__ __forceinline__ uint32_t pack_bf16x2(__nv_bfloat16 lo16, __nv_bfloat16 hi16) {
    return ((uint32_t)__bfloat16_as_ushort(hi16) << 16) | (uint32_t)__bfloat16_as_ushort(lo16);
}

__device__ __forceinline__ void mma16816(float* c, const uint32_t* a, uint32_t b0, uint32_t b1) {
    asm volatile(
        "mma.sync.aligned.m16n8k16.row.col.f32.bf16.bf16.f32 "
        "{%0,%1,%2,%3}, {%4,%5,%6,%7}, {%8,%9}, {%0,%1,%2,%3};"
        : "+f"(c[0]), "+f"(c[1]), "+f"(c[2]), "+f"(c[3])
        : "r"(a[0]), "r"(a[1]), "r"(a[2]), "r"(a[3]), "r"(b0), "r"(b1));
}

__device__ __forceinline__ void ldmatrix4(uint32_t* r, uint32_t addr) {
    asm volatile("ldmatrix.sync.aligned.m8n8.x4.shared.b16 {%0,%1,%2,%3}, [%4];"
                 : "=r"(r[0]), "=r"(r[1]), "=r"(r[2]), "=r"(r[3]) : "r"(addr));
}

// ---------------- kernel 0: fused zero + all weight conversions ----------------
__global__ void prelude_kernel(const float* __restrict__ W1, const float* __restrict__ r0,
                               const float* __restrict__ r1, const float* __restrict__ oW) {
    const int b = blockIdx.x;
    const int tid = threadIdx.x;
    if (b < 8192) {
        const int idx = b * 256 + tid;
        g_ref_sums[idx] = 0.f;
        g_alt_sums[idx] = 0.f;
        if (idx < V) { g_ref_cnt[idx] = 0; g_alt_cnt[idx] = 0; }
        return;
    }
    int cb = b - 8192;
    const float* W;
    uint4* dst;
    if (cb < 64)       { W = W1; dst = g_W1i; }
    else if (cb < 256) { W = r0; dst = g_r0i; cb -= 64; }
    else if (cb < 320) { W = r1; dst = g_r1i; cb -= 256; }
    else               { W = oW; dst = g_oWi; cb -= 320; }
    const int idx = cb * 256 + tid;
    const int lane = idx & 31;
    const int nt   = (idx >> 5) & 31;
    const int kt   = idx >> 10;
    const int n = nt * 8 + (lane >> 2);
    const int kbase = kt * 16 + (lane & 3) * 2;
    uint32_t hv[2], lv[2];
    #pragma unroll
    for (int r = 0; r < 2; r++) {
        const int k = kbase + 8 * r;
        const float w0 = W[k * 256 + n];
        const float w1 = W[(k + 1) * 256 + n];
        __nv_bfloat16 h0 = __float2bfloat16(w0), h1 = __float2bfloat16(w1);
        __nv_bfloat16 l0 = __float2bfloat16(w0 - __bfloat162float(h0));
        __nv_bfloat16 l1 = __float2bfloat16(w1 - __bfloat162float(h1));
        hv[r] = pack_bf16x2(h0, h1);
        lv[r] = pack_bf16x2(l0, l1);
    }
    dst[idx] = make_uint4(hv[0], hv[1], lv[0], lv[1]);
}

// ---------------- kernel 1: fused phi MLP + segment reduce ----------------
// 2-term split: y = sigmoid(bf16(h) @ (W1h + W1l) + b1). h stored bf16 (hi only).
// smem: h[64][264 bf16] ; xsT ; segs. ys (f32, 64x257) overlays h+xsT after mma.
#define HPITCH_B 528
#define SM_HS    0
#define SM_XST   (TILE_R * HPITCH_B)               // 33792
#define SM_SEGS  65792                             // after ys span (64*257*4 = 65792)
#define PHI_SMEM_TOTAL (SM_SEGS + 512)             // 66304
#define YPITCH 257

__global__ __launch_bounds__(256, 2) void phi_mma_kernel(
    const float* __restrict__ reads,
    const int* __restrict__ ref_seg, const int* __restrict__ alt_seg,
    const float* __restrict__ W0, const float* __restrict__ b0,
    const float* __restrict__ b1)
{
    extern __shared__ char sm[];
    const uint32_t smb = (uint32_t)__cvta_generic_to_shared(sm);
    float* xsT  = (float*)(sm + SM_XST);
    int*   segs = (int*)(sm + SM_SEGS);
    float* ys   = (float*)sm;

    const int tid = threadIdx.x;
    const long base = (long)blockIdx.x * TILE_R;
    const bool is_alt = (base >= NREF);
    const int* seg_src = is_alt ? (alt_seg + (base - NREF)) : (ref_seg + base);

    for (int idx = tid; idx < TILE_R * FREAD; idx += 256) {
        int r = idx / FREAD, c = idx % FREAD;
        xsT[c * TILE_R + r] = reads[(base + r) * FREAD + c];
    }
    if (tid < TILE_R) segs[tid] = seg_src[tid];
    __syncthreads();

    if (tid < TILE_R) {
        int* cnt = is_alt ? g_alt_cnt : g_ref_cnt;
        atomicAdd(&cnt[segs[tid]], 1);
    }

    // stage 1: h = lrelu(x @ W0 + b0) -> bf16 in smem (thread = column)
    {
        const int j = tid;
        float w[FREAD];
        #pragma unroll
        for (int k = 0; k < FREAD; k++) w[k] = W0[k * H + j];
        const float bb = b0[j];
        for (int r = 0; r < TILE_R; r += 4) {
            float a0 = bb, a1 = bb, a2 = bb, a3 = bb;
            #pragma unroll
            for (int k = 0; k < FREAD; k++) {
                const float4 a = *(const float4*)&xsT[k * TILE_R + r];
                a0 = fmaf(a.x, w[k], a0); a1 = fmaf(a.y, w[k], a1);
                a2 = fmaf(a.z, w[k], a2); a3 = fmaf(a.w, w[k], a3);
            }
            float hv[4] = {lrelu(a0), lrelu(a1), lrelu(a2), lrelu(a3)};
            #pragma unroll
            for (int q = 0; q < 4; q++) {
                *(__nv_bfloat16*)(sm + SM_HS + (r + q) * HPITCH_B + j * 2) =
                    __float2bfloat16(hv[q]);
            }
        }
    }
    __syncthreads();

    // stage 2: D[64][256] = bf16(h) @ (W1h + W1l)
    const int wid = tid >> 5, lane = tid & 31;
    const int wr = wid >> 2, wc = wid & 3;
    const int rowbase = wr * 32;

    float acc[2][8][4];
    #pragma unroll
    for (int mt = 0; mt < 2; mt++)
        #pragma unroll
        for (int j = 0; j < 8; j++)
            #pragma unroll
            for (int q = 0; q < 4; q++) acc[mt][j][q] = 0.f;

    for (int kt = 0; kt < 16; kt++) {
        uint4 Bv[8];
        #pragma unroll
        for (int j = 0; j < 8; j++)
            Bv[j] = __ldg(&g_W1i[kt * 1024 + ((wc * 8 + j) * 32 + lane)]);
        uint32_t ah[2][4];
        #pragma unroll
        for (int mt = 0; mt < 2; mt++) {
            const uint32_t addr = smb + SM_HS
                + (uint32_t)(rowbase + mt * 16 + (lane & 15)) * HPITCH_B
                + ((uint32_t)(lane >> 4)) * 16 + (uint32_t)kt * 32;
            ldmatrix4(ah[mt], addr);
        }
        #pragma unroll
        for (int j = 0; j < 8; j++) {
            #pragma unroll
            for (int mt = 0; mt < 2; mt++) {
                mma16816(acc[mt][j], ah[mt], Bv[j].x, Bv[j].y);
                mma16816(acc[mt][j], ah[mt], Bv[j].z, Bv[j].w);
            }
        }
    }
    __syncthreads();

    // epilogue: bias + sigmoid -> ys[64][257] (overlays h/xsT; both dead)
    {
        const int colb = wc * 64 + 2 * (lane & 3);
        float bias0[8], bias1[8];
        #pragma unroll
        for (int j = 0; j < 8; j++) {
            bias0[j] = __ldg(&b1[colb + j * 8]);
            bias1[j] = __ldg(&b1[colb + j * 8 + 1]);
        }
        #pragma unroll
        for (int mt = 0; mt < 2; mt++) {
            const int row = rowbase + mt * 16 + (lane >> 2);
            #pragma unroll
            for (int j = 0; j < 8; j++) {
                const int col = colb + j * 8;
                ys[row * YPITCH + col]           = sigmoidf_(acc[mt][j][0] + bias0[j]);
                ys[row * YPITCH + col + 1]       = sigmoidf_(acc[mt][j][1] + bias1[j]);
                ys[(row + 8) * YPITCH + col]     = sigmoidf_(acc[mt][j][2] + bias0[j]);
                ys[(row + 8) * YPITCH + col + 1] = sigmoidf_(acc[mt][j][3] + bias1[j]);
            }
        }
    }
    __syncthreads();

    // sorted-run segment reduction: thread = column
    {
        float* sums = is_alt ? g_alt_sums : g_ref_sums;
        const int c = tid;
        int cur = segs[0];
        float a = 0.f;
        #pragma unroll 4
        for (int r = 0; r < TILE_R; r++) {
            int s = segs[r];
            if (s != cur) { atomicAdd(&sums[cur * H + c], a); a = 0.f; cur = s; }
            a += ys[r * YPITCH + c];
        }
        atomicAdd(&sums[cur * H + c], a);
    }
}

// ---------------- kernel 2: rho MLP + per-type heads (X computed in-kernel) ----------------
#define SM_XH    0
#define SM_XL    16896
#define SM_Z1H   33792
#define SM_Z1L   50688
#define SM_LOG   67584
#define SM_OM    67712
#define SM_INFO  76928
#define SM_RCP   78080
#define HEAD_SMEM_TOTAL 78336

__global__ __launch_bounds__(256, 2) void head_mma_kernel(
    const int* __restrict__ vtypes,
    const float* __restrict__ info,
    const float* __restrict__ omW0,  const float* __restrict__ omb0,
    const float* __restrict__ rhob0, const float* __restrict__ rhob1,
    const float* __restrict__ outb1, const float* __restrict__ outb2,
    const float* __restrict__ outW2,
    const float* __restrict__ conf,  const float* __restrict__ max_logit,
    float* __restrict__ out)
{
    extern __shared__ char sm[];
    const uint32_t smb = (uint32_t)__cvta_generic_to_shared(sm);
    float* logits_s = (float*)(sm + SM_LOG);
    float* om_s     = (float*)(sm + SM_OM);
    float* info_s   = (float*)(sm + SM_INFO);
    float* rcp_s    = (float*)(sm + SM_RCP);

    const int tid = threadIdx.x;
    const int wid = tid >> 5, lane = tid & 31;
    const int wr = wid >> 2, wc = wid & 3;
    const int v0 = blockIdx.x * 32;

    for (int i = tid; i < FINFO * H; i += 256) om_s[i] = omW0[i];
    for (int i = tid; i < 32 * FINFO; i += 256) info_s[i] = info[v0 * FINFO + i];
    if (tid < 32) {
        rcp_s[tid]      = 1.0f / (float)max(g_ref_cnt[v0 + tid], 1);
        rcp_s[tid + 32] = 1.0f / (float)max(g_alt_cnt[v0 + tid], 1);
    }
    __syncthreads();

    float acc[8][4];

    // ---- phase 1: z1 = lrelu(X @ rhoW0 + rhob0), K = 768 in 3 chunks of 256
    #pragma unroll
    for (int j = 0; j < 8; j++)
        #pragma unroll
        for (int q = 0; q < 4; q++) acc[j][q] = 0.f;

    for (int kb = 0; kb < 3; kb++) {
        if (kb < 2) {
            const float* sums = kb ? g_alt_sums : g_ref_sums;
            const float* rr   = rcp_s + kb * 32;
            for (int i = tid; i < 32 * H; i += 256) {
                const int c = i & 255, r = i >> 8;
                const float val = __ldg(&sums[(size_t)(v0 + r) * H + c]) * rr[r];
                __nv_bfloat16 hi = __float2bfloat16(val);
                *(__nv_bfloat16*)(sm + SM_XH + r * HPITCH_B + c * 2) = hi;
                *(__nv_bfloat16*)(sm + SM_XL + r * HPITCH_B + c * 2) =
                    __float2bfloat16(val - __bfloat162float(hi));
            }
        } else {
            for (int i = tid; i < 32 * H; i += 256) {
                const int c = i & 255, r = i >> 8;
                float z = __ldg(&omb0[c]);
                #pragma unroll
                for (int k = 0; k < FINFO; k++)
                    z = fmaf(info_s[r * FINFO + k], om_s[k * H + c], z);
                const float val = sigmoidf_(z);
                __nv_bfloat16 hi = __float2bfloat16(val);
                *(__nv_bfloat16*)(sm + SM_XH + r * HPITCH_B + c * 2) = hi;
                *(__nv_bfloat16*)(sm + SM_XL + r * HPITCH_B + c * 2) =
                    __float2bfloat16(val - __bfloat162float(hi));
            }
        }
        __syncthreads();
        for (int kt = 0; kt < 16; kt++) {
            const int g = kb * 16 + kt;
            uint4 Bv[8];
            #pragma unroll
            for (int j = 0; j < 8; j++)
                Bv[j] = __ldg(&g_r0i[g * 1024 + ((wc * 8 + j) * 32 + lane)]);
            uint32_t ah[4], al[4];
            const uint32_t addr = smb + SM_XH
                + (uint32_t)(wr * 16 + (lane & 15)) * HPITCH_B
                + ((uint32_t)(lane >> 4)) * 16 + (uint32_t)kt * 32;
            ldmatrix4(ah, addr);
            ldmatrix4(al, addr + (SM_XL - SM_XH));
            #pragma unroll
            for (int j = 0; j < 8; j++) {
                mma16816(acc[j], ah, Bv[j].x, Bv[j].y);
                mma16816(acc[j], ah, Bv[j].z, Bv[j].w);
                mma16816(acc[j], al, Bv[j].x, Bv[j].y);
            }
        }
        __syncthreads();
    }
    {
        const int r0 = wr * 16 + (lane >> 2);
        #pragma unroll
        for (int j = 0; j < 8; j++) {
            const int c0 = wc * 64 + j * 8 + (lane & 3) * 2;
            const float b0v = __ldg(&rhob0[c0]), b1v = __ldg(&rhob0[c0 + 1]);
            float vv[4] = {lrelu(acc[j][0] + b0v), lrelu(acc[j][1] + b1v),
                           lrelu(acc[j][2] + b0v), lrelu(acc[j][3] + b1v)};
            #pragma unroll
            for (int q = 0; q < 4; q++) {
                const int rr = (q < 2) ? r0 : r0 + 8;
                const int cc = c0 + (q & 1);
                __nv_bfloat16 hi = __float2bfloat16(vv[q]);
                *(__nv_bfloat16*)(sm + SM_Z1H + rr * HPITCH_B + cc * 2) = hi;
                *(__nv_bfloat16*)(sm + SM_Z1L + rr * HPITCH_B + cc * 2) =
                    __float2bfloat16(vv[q] - __bfloat162float(hi));
            }
        }
    }
    __syncthreads();

    // ---- phase 2: agg = z1 @ rhoW1 + rhob1 (K=256)
    #pragma unroll
    for (int j = 0; j < 8; j++)
        #pragma unroll
        for (int q = 0; q < 4; q++) acc[j][q] = 0.f;

    for (int kt = 0; kt < 16; kt++) {
        uint4 Bv[8];
        #pragma unroll
        for (int j = 0; j < 8; j++)
            Bv[j] = __ldg(&g_r1i[kt * 1024 + ((wc * 8 + j) * 32 + lane)]);
        uint32_t ah[4], al[4];
        const uint32_t addr = smb + SM_Z1H
            + (uint32_t)(wr * 16 + (lane & 15)) * HPITCH_B
            + ((uint32_t)(lane >> 4)) * 16 + (uint32_t)kt * 32;
        ldmatrix4(ah, addr);
        ldmatrix4(al, addr + (SM_Z1L - SM_Z1H));
        #pragma unroll
        for (int j = 0; j < 8; j++) {
            mma16816(acc[j], ah, Bv[j].x, Bv[j].y);
            mma16816(acc[j], ah, Bv[j].z, Bv[j].w);
            mma16816(acc[j], al, Bv[j].x, Bv[j].y);
        }
    }
    {
        const int r0 = wr * 16 + (lane >> 2);
        #pragma unroll
        for (int j = 0; j < 8; j++) {
            const int c0 = wc * 64 + j * 8 + (lane & 3) * 2;
            const float b0v = __ldg(&rhob1[c0]), b1v = __ldg(&rhob1[c0 + 1]);
            float vv[4] = {acc[j][0] + b0v, acc[j][1] + b1v,
                           acc[j][2] + b0v, acc[j][3] + b1v};
            #pragma unroll
            for (int q = 0; q < 4; q++) {
                const int rr = (q < 2) ? r0 : r0 + 8;
                const int cc = c0 + (q & 1);
                __nv_bfloat16 hi = __float2bfloat16(vv[q]);
                *(__nv_bfloat16*)(sm + SM_XH + rr * HPITCH_B + cc * 2) = hi;
                *(__nv_bfloat16*)(sm + SM_XL + rr * HPITCH_B + cc * 2) =
                    __float2bfloat16(vv[q] - __bfloat162float(hi));
            }
        }
    }
    __syncthreads();

    // ---- phase 3: per-type out heads
    const float ml = *max_logit;
    for (int t = 0; t < 3; t++) {
        if (tid < 32) logits_s[tid] = 0.f;
        __syncthreads();

        #pragma unroll
        for (int j = 0; j < 8; j++)
            #pragma unroll
            for (int q = 0; q < 4; q++) acc[j][q] = 0.f;

        for (int kt = 0; kt < 16; kt++) {
            const int g = t * 16 + kt;
            uint4 Bv[8];
            #pragma unroll
            for (int j = 0; j < 8; j++)
                Bv[j] = __ldg(&g_oWi[g * 1024 + ((wc * 8 + j) * 32 + lane)]);
            uint32_t ah[4], al[4];
            const uint32_t addr = smb + SM_XH
                + (uint32_t)(wr * 16 + (lane & 15)) * HPITCH_B
                + ((uint32_t)(lane >> 4)) * 16 + (uint32_t)kt * 32;
            ldmatrix4(ah, addr);
            ldmatrix4(al, addr + (SM_XL - SM_XH));
            #pragma unroll
            for (int j = 0; j < 8; j++) {
                mma16816(acc[j], ah, Bv[j].x, Bv[j].y);
                mma16816(acc[j], ah, Bv[j].z, Bv[j].w);
                mma16816(acc[j], al, Bv[j].x, Bv[j].y);
            }
        }

        float p0 = 0.f, p1 = 0.f;
        #pragma unroll
        for (int j = 0; j < 8; j++) {
            const int c0 = wc * 64 + j * 8 + (lane & 3) * 2;
            const float bb0 = __ldg(&outb1[t * H + c0]);
            const float bb1 = __ldg(&outb1[t * H + c0 + 1]);
            const float w20 = __ldg(&outW2[t * H + c0]);
            const float w21 = __ldg(&outW2[t * H + c0 + 1]);
            p0 += lrelu(acc[j][0] + bb0) * w20 + lrelu(acc[j][1] + bb1) * w21;
            p1 += lrelu(acc[j][2] + bb0) * w20 + lrelu(acc[j][3] + bb1) * w21;
        }
        p0 += __shfl_xor_sync(0xffffffffu, p0, 1);
        p0 += __shfl_xor_sync(0xffffffffu, p0, 2);
        p1 += __shfl_xor_sync(0xffffffffu, p1, 1);
        p1 += __shfl_xor_sync(0xffffffffu, p1, 2);
        if ((lane & 3) == 0) {
            const int r0 = wr * 16 + (lane >> 2);
            atomicAdd(&logits_s[r0], p0);
            atomicAdd(&logits_s[r0 + 8], p1);
        }
        __syncthreads();
        if (tid < 32) {
            const int v = v0 + tid;
            if (vtypes[v] == t) {
                float l = logits_s[tid] + outb2[t];
                const int ci = min(g_alt_cnt[v], MAX_ALT);
                l *= conf[ci];
                out[v] = ml * tanhf(l / ml);
            }
        }
        __syncthreads();
    }
}

// ---------------- launch ----------------
extern "C" void kernel_launch(void* const* d_in, const int* in_sizes, int n_in,
                              void* d_out, int out_size)
{
    const float* reads  = (const float*)d_in[0];
    const float* info   = (const float*)d_in[1];
    const int*   refseg = (const int*)  d_in[2];
    const int*   altseg = (const int*)  d_in[3];
    const int*   vtypes = (const int*)  d_in[4];
    const float* phiW0  = (const float*)d_in[5];
    const float* phib0  = (const float*)d_in[6];
    const float* phiW1  = (const float*)d_in[7];
    const float* phib1  = (const float*)d_in[8];
    const float* omW0   = (const float*)d_in[9];
    const float* omb0   = (const float*)d_in[10];
    const float* rhoW0  = (const float*)d_in[11];
    const float* rhob0  = (const float*)d_in[12];
    const float* rhoW1  = (const float*)d_in[13];
    const float* rhob1  = (const float*)d_in[14];
    const float* outW1  = (const float*)d_in[15];
    const float* outb1  = (const float*)d_in[16];
    const float* outW2  = (const float*)d_in[17];
    const float* outb2  = (const float*)d_in[18];
    const float* conf   = (const float*)d_in[19];
    const float* maxl   = (const float*)d_in[20];
    float* out = (float*)d_out;

    cudaFuncSetAttribute(phi_mma_kernel,  cudaFuncAttributeMaxDynamicSharedMemorySize, PHI_SMEM_TOTAL);
    cudaFuncSetAttribute(head_mma_kernel, cudaFuncAttributeMaxDynamicSharedMemorySize, HEAD_SMEM_TOTAL);

    prelude_kernel<<<8704, 256>>>(phiW1, rhoW0, rhoW1, outW1);
    phi_mma_kernel<<<(NREF + NALT) / TILE_R, 256, PHI_SMEM_TOTAL>>>(
        reads, refseg, altseg, phiW0, phib0, phib1);
    head_mma_kernel<<<V / 32, 256, HEAD_SMEM_TOTAL>>>(
        vtypes, info, omW0, omb0, rhob0, rhob1, outb1, outb2, outW2, conf, maxl, out);
}

// round 11
// speedup vs baseline: 1.2922x; 1.2922x over previous
#include <cuda_runtime.h>
#include <cuda_bf16.h>
#include <math.h>
#include <stdint.h>

#define V     8192
#define NREF  262144
#define NALT  131072
#define FREAD 11
#define FINFO 9
#define H     256
#define MAX_ALT 10

#define TILE_R 64

// ---------------- scratch ----------------
__device__ float g_ref_sums[V * H];
__device__ float g_alt_sums[V * H];
__device__ int   g_ref_cnt[V];
__device__ int   g_alt_cnt[V];
// weights, interleaved mma fragments: uint4 {hi_r0, hi_r1, lo_r0, lo_r1} per [kt][nt(32)][lane(32)]
__device__ __align__(16) uint4 g_W1i[16 * 1024];
__device__ __align__(16) uint4 g_r0i[48 * 1024];
__device__ __align__(16) uint4 g_r1i[16 * 1024];
__device__ __align__(16) uint4 g_oWi[48 * 1024];

// ---------------- helpers ----------------
__device__ __forceinline__ float lrelu(float x) { return x > 0.f ? x : 0.01f * x; }
__device__ __forceinline__ float sigmoidf_(float x) { return 1.f / (1.f + __expf(-x)); }

__device__ __forceinline__ uint32_t pack_bf16x2(__nv_bfloat16 lo16, __nv_bfloat16 hi16) {
    return ((uint32_t)__bfloat16_as_ushort(hi16) << 16) | (uint32_t)__bfloat16_as_ushort(lo16);
}

__device__ __forceinline__ void mma16816(float* c, const uint32_t* a, uint32_t b0, uint32_t b1) {
    asm volatile(
        "mma.sync.aligned.m16n8k16.row.col.f32.bf16.bf16.f32 "
        "{%0,%1,%2,%3}, {%4,%5,%6,%7}, {%8,%9}, {%0,%1,%2,%3};"
        : "+f"(c[0]), "+f"(c[1]), "+f"(c[2]), "+f"(c[3])
        : "r"(a[0]), "r"(a[1]), "r"(a[2]), "r"(a[3]), "r"(b0), "r"(b1));
}

__device__ __forceinline__ void ldmatrix4(uint32_t* r, uint32_t addr) {
    asm volatile("ldmatrix.sync.aligned.m8n8.x4.shared.b16 {%0,%1,%2,%3}, [%4];"
                 : "=r"(r[0]), "=r"(r[1]), "=r"(r[2]), "=r"(r[3]) : "r"(addr));
}

__device__ __forceinline__ void cpasync16(uint32_t dst_smem, const void* src) {
    asm volatile("cp.async.cg.shared.global [%0], [%1], 16;" :: "r"(dst_smem), "l"(src) : "memory");
}

// ---------------- kernel 0: fused zero + all weight conversions ----------------
__global__ void prelude_kernel(const float* __restrict__ W1, const float* __restrict__ r0,
                               const float* __restrict__ r1, const float* __restrict__ oW) {
    const int b = blockIdx.x;
    const int tid = threadIdx.x;
    if (b < 8192) {
        const int idx = b * 256 + tid;
        g_ref_sums[idx] = 0.f;
        g_alt_sums[idx] = 0.f;
        if (idx < V) { g_ref_cnt[idx] = 0; g_alt_cnt[idx] = 0; }
        return;
    }
    int cb = b - 8192;
    const float* W;
    uint4* dst;
    if (cb < 64)       { W = W1; dst = g_W1i; }
    else if (cb < 256) { W = r0; dst = g_r0i; cb -= 64; }
    else if (cb < 320) { W = r1; dst = g_r1i; cb -= 256; }
    else               { W = oW; dst = g_oWi; cb -= 320; }
    const int idx = cb * 256 + tid;
    const int lane = idx & 31;
    const int nt   = (idx >> 5) & 31;
    const int kt   = idx >> 10;
    const int n = nt * 8 + (lane >> 2);
    const int kbase = kt * 16 + (lane & 3) * 2;
    uint32_t hv[2], lv[2];
    #pragma unroll
    for (int r = 0; r < 2; r++) {
        const int k = kbase + 8 * r;
        const float w0 = W[k * 256 + n];
        const float w1 = W[(k + 1) * 256 + n];
        __nv_bfloat16 h0 = __float2bfloat16(w0), h1 = __float2bfloat16(w1);
        __nv_bfloat16 l0 = __float2bfloat16(w0 - __bfloat162float(h0));
        __nv_bfloat16 l1 = __float2bfloat16(w1 - __bfloat162float(h1));
        hv[r] = pack_bf16x2(h0, h1);
        lv[r] = pack_bf16x2(l0, l1);
    }
    dst[idx] = make_uint4(hv[0], hv[1], lv[0], lv[1]);
}

// ---------------- kernel 1: fused phi MLP + segment reduce ----------------
// 2-term split (h bf16; W1 = hi+lo), cp.async double-buffered B in smem.
// smem: h[64][264 bf16] | B 2x16KB | xsT | segs.  ys (64x257 f32) overlays h+B after mma.
#define HPITCH_B 528
#define SM_HS    0
#define SM_B     33792                      // 2 x 16384, ends 66560
#define SM_XST   66560                      // 11*64*4 = 2816
#define SM_SEGS  69376                      // 256
#define PHI_SMEM_TOTAL 69888
#define YPITCH 257

__global__ __launch_bounds__(256, 2) void phi_mma_kernel(
    const float* __restrict__ reads,
    const int* __restrict__ ref_seg, const int* __restrict__ alt_seg,
    const float* __restrict__ W0, const float* __restrict__ b0,
    const float* __restrict__ b1)
{
    extern __shared__ char sm[];
    const uint32_t smb = (uint32_t)__cvta_generic_to_shared(sm);
    float* xsT  = (float*)(sm + SM_XST);
    int*   segs = (int*)(sm + SM_SEGS);
    float* ys   = (float*)sm;

    const int tid = threadIdx.x;
    const long base = (long)blockIdx.x * TILE_R;
    const bool is_alt = (base >= NREF);
    const int* seg_src = is_alt ? (alt_seg + (base - NREF)) : (ref_seg + base);

    // prefetch B chunk kt=0 into buffer 0 (before anything else; arrives during stage 1)
    #pragma unroll
    for (int i = 0; i < 4; i++) {
        const int c = tid + 256 * i;        // 0..1023 16B chunks
        cpasync16(smb + SM_B + c * 16, &g_W1i[c]);
    }
    asm volatile("cp.async.commit_group;" ::: "memory");

    for (int idx = tid; idx < TILE_R * FREAD; idx += 256) {
        int r = idx / FREAD, c = idx % FREAD;
        xsT[c * TILE_R + r] = reads[(base + r) * FREAD + c];
    }
    if (tid < TILE_R) segs[tid] = seg_src[tid];
    __syncthreads();

    if (tid < TILE_R) {
        int* cnt = is_alt ? g_alt_cnt : g_ref_cnt;
        atomicAdd(&cnt[segs[tid]], 1);
    }

    // stage 1: h = lrelu(x @ W0 + b0) -> bf16 in smem (thread = column)
    {
        const int j = tid;
        float w[FREAD];
        #pragma unroll
        for (int k = 0; k < FREAD; k++) w[k] = W0[k * H + j];
        const float bb = b0[j];
        for (int r = 0; r < TILE_R; r += 4) {
            float a0 = bb, a1 = bb, a2 = bb, a3 = bb;
            #pragma unroll
            for (int k = 0; k < FREAD; k++) {
                const float4 a = *(const float4*)&xsT[k * TILE_R + r];
                a0 = fmaf(a.x, w[k], a0); a1 = fmaf(a.y, w[k], a1);
                a2 = fmaf(a.z, w[k], a2); a3 = fmaf(a.w, w[k], a3);
            }
            float hv[4] = {lrelu(a0), lrelu(a1), lrelu(a2), lrelu(a3)};
            #pragma unroll
            for (int q = 0; q < 4; q++) {
                *(__nv_bfloat16*)(sm + SM_HS + (r + q) * HPITCH_B + j * 2) =
                    __float2bfloat16(hv[q]);
            }
        }
    }
    __syncthreads();

    // stage 2: D[64][256] = bf16(h) @ (W1h + W1l), pipelined B through smem
    const int wid = tid >> 5, lane = tid & 31;
    const int wr = wid >> 2, wc = wid & 3;
    const int rowbase = wr * 32;

    float acc[2][8][4];
    #pragma unroll
    for (int mt = 0; mt < 2; mt++)
        #pragma unroll
        for (int j = 0; j < 8; j++)
            #pragma unroll
            for (int q = 0; q < 4; q++) acc[mt][j][q] = 0.f;

    for (int kt = 0; kt < 16; kt++) {
        if (kt < 15) {
            const int s = (kt + 1) & 1;
            #pragma unroll
            for (int i = 0; i < 4; i++) {
                const int c = tid + 256 * i;
                cpasync16(smb + SM_B + s * 16384 + c * 16, &g_W1i[(kt + 1) * 1024 + c]);
            }
            asm volatile("cp.async.commit_group;" ::: "memory");
            asm volatile("cp.async.wait_group 1;" ::: "memory");
        } else {
            asm volatile("cp.async.wait_group 0;" ::: "memory");
        }
        __syncthreads();   // buf[kt&1] visible to all warps

        uint32_t ah[2][4];
        #pragma unroll
        for (int mt = 0; mt < 2; mt++) {
            const uint32_t addr = smb + SM_HS
                + (uint32_t)(rowbase + mt * 16 + (lane & 15)) * HPITCH_B
                + ((uint32_t)(lane >> 4)) * 16 + (uint32_t)kt * 32;
            ldmatrix4(ah[mt], addr);
        }
        const uint4* bbuf = (const uint4*)(sm + SM_B + (kt & 1) * 16384);
        uint4 Bv[8];
        #pragma unroll
        for (int j = 0; j < 8; j++)
            Bv[j] = bbuf[(wc * 8 + j) * 32 + lane];
        #pragma unroll
        for (int j = 0; j < 8; j++) {
            #pragma unroll
            for (int mt = 0; mt < 2; mt++) {
                mma16816(acc[mt][j], ah[mt], Bv[j].x, Bv[j].y);
                mma16816(acc[mt][j], ah[mt], Bv[j].z, Bv[j].w);
            }
        }
        __syncthreads();   // all reads of buf[kt&1] done before it is restaged
    }

    // epilogue: bias + sigmoid -> ys[64][257] (overlays h + B; both dead)
    {
        const int colb = wc * 64 + 2 * (lane & 3);
        float bias0[8], bias1[8];
        #pragma unroll
        for (int j = 0; j < 8; j++) {
            bias0[j] = __ldg(&b1[colb + j * 8]);
            bias1[j] = __ldg(&b1[colb + j * 8 + 1]);
        }
        #pragma unroll
        for (int mt = 0; mt < 2; mt++) {
            const int row = rowbase + mt * 16 + (lane >> 2);
            #pragma unroll
            for (int j = 0; j < 8; j++) {
                const int col = colb + j * 8;
                ys[row * YPITCH + col]           = sigmoidf_(acc[mt][j][0] + bias0[j]);
                ys[row * YPITCH + col + 1]       = sigmoidf_(acc[mt][j][1] + bias1[j]);
                ys[(row + 8) * YPITCH + col]     = sigmoidf_(acc[mt][j][2] + bias0[j]);
                ys[(row + 8) * YPITCH + col + 1] = sigmoidf_(acc[mt][j][3] + bias1[j]);
            }
        }
    }
    __syncthreads();

    // sorted-run segment reduction: thread = column
    {
        float* sums = is_alt ? g_alt_sums : g_ref_sums;
        const int c = tid;
        int cur = segs[0];
        float a = 0.f;
        #pragma unroll 4
        for (int r = 0; r < TILE_R; r++) {
            int s = segs[r];
            if (s != cur) { atomicAdd(&sums[cur * H + c], a); a = 0.f; cur = s; }
            a += ys[r * YPITCH + c];
        }
        atomicAdd(&sums[cur * H + c], a);
    }
}

// ---------------- kernel 2: rho MLP + per-type heads (X computed in-kernel) ----------------
#define SM_XH    0
#define SM_XL    16896
#define SM_Z1H   33792
#define SM_Z1L   50688
#define SM_LOG   67584
#define SM_OM    67712
#define SM_INFO  76928
#define SM_RCP   78080
#define HEAD_SMEM_TOTAL 78336

__global__ __launch_bounds__(256, 2) void head_mma_kernel(
    const int* __restrict__ vtypes,
    const float* __restrict__ info,
    const float* __restrict__ omW0,  const float* __restrict__ omb0,
    const float* __restrict__ rhob0, const float* __restrict__ rhob1,
    const float* __restrict__ outb1, const float* __restrict__ outb2,
    const float* __restrict__ outW2,
    const float* __restrict__ conf,  const float* __restrict__ max_logit,
    float* __restrict__ out)
{
    extern __shared__ char sm[];
    const uint32_t smb = (uint32_t)__cvta_generic_to_shared(sm);
    float* logits_s = (float*)(sm + SM_LOG);
    float* om_s     = (float*)(sm + SM_OM);
    float* info_s   = (float*)(sm + SM_INFO);
    float* rcp_s    = (float*)(sm + SM_RCP);

    const int tid = threadIdx.x;
    const int wid = tid >> 5, lane = tid & 31;
    const int wr = wid >> 2, wc = wid & 3;
    const int v0 = blockIdx.x * 32;

    for (int i = tid; i < FINFO * H; i += 256) om_s[i] = omW0[i];
    for (int i = tid; i < 32 * FINFO; i += 256) info_s[i] = info[v0 * FINFO + i];
    if (tid < 32) {
        rcp_s[tid]      = 1.0f / (float)max(g_ref_cnt[v0 + tid], 1);
        rcp_s[tid + 32] = 1.0f / (float)max(g_alt_cnt[v0 + tid], 1);
    }
    __syncthreads();

    float acc[8][4];

    // ---- phase 1: z1 = lrelu(X @ rhoW0 + rhob0), K = 768 in 3 chunks of 256
    #pragma unroll
    for (int j = 0; j < 8; j++)
        #pragma unroll
        for (int q = 0; q < 4; q++) acc[j][q] = 0.f;

    for (int kb = 0; kb < 3; kb++) {
        if (kb < 2) {
            const float* sums = kb ? g_alt_sums : g_ref_sums;
            const float* rr   = rcp_s + kb * 32;
            for (int i = tid; i < 32 * H; i += 256) {
                const int c = i & 255, r = i >> 8;
                const float val = __ldg(&sums[(size_t)(v0 + r) * H + c]) * rr[r];
                __nv_bfloat16 hi = __float2bfloat16(val);
                *(__nv_bfloat16*)(sm + SM_XH + r * HPITCH_B + c * 2) = hi;
                *(__nv_bfloat16*)(sm + SM_XL + r * HPITCH_B + c * 2) =
                    __float2bfloat16(val - __bfloat162float(hi));
            }
        } else {
            for (int i = tid; i < 32 * H; i += 256) {
                const int c = i & 255, r = i >> 8;
                float z = __ldg(&omb0[c]);
                #pragma unroll
                for (int k = 0; k < FINFO; k++)
                    z = fmaf(info_s[r * FINFO + k], om_s[k * H + c], z);
                const float val = sigmoidf_(z);
                __nv_bfloat16 hi = __float2bfloat16(val);
                *(__nv_bfloat16*)(sm + SM_XH + r * HPITCH_B + c * 2) = hi;
                *(__nv_bfloat16*)(sm + SM_XL + r * HPITCH_B + c * 2) =
                    __float2bfloat16(val - __bfloat162float(hi));
            }
        }
        __syncthreads();
        for (int kt = 0; kt < 16; kt++) {
            const int g = kb * 16 + kt;
            uint4 Bv[8];
            #pragma unroll
            for (int j = 0; j < 8; j++)
                Bv[j] = __ldg(&g_r0i[g * 1024 + ((wc * 8 + j) * 32 + lane)]);
            uint32_t ah[4], al[4];
            const uint32_t addr = smb + SM_XH
                + (uint32_t)(wr * 16 + (lane & 15)) * HPITCH_B
                + ((uint32_t)(lane >> 4)) * 16 + (uint32_t)kt * 32;
            ldmatrix4(ah, addr);
            ldmatrix4(al, addr + (SM_XL - SM_XH));
            #pragma unroll
            for (int j = 0; j < 8; j++) {
                mma16816(acc[j], ah, Bv[j].x, Bv[j].y);
                mma16816(acc[j], ah, Bv[j].z, Bv[j].w);
                mma16816(acc[j], al, Bv[j].x, Bv[j].y);
            }
        }
        __syncthreads();
    }
    {
        const int r0 = wr * 16 + (lane >> 2);
        #pragma unroll
        for (int j = 0; j < 8; j++) {
            const int c0 = wc * 64 + j * 8 + (lane & 3) * 2;
            const float b0v = __ldg(&rhob0[c0]), b1v = __ldg(&rhob0[c0 + 1]);
            float vv[4] = {lrelu(acc[j][0] + b0v), lrelu(acc[j][1] + b1v),
                           lrelu(acc[j][2] + b0v), lrelu(acc[j][3] + b1v)};
            #pragma unroll
            for (int q = 0; q < 4; q++) {
                const int rr = (q < 2) ? r0 : r0 + 8;
                const int cc = c0 + (q & 1);
                __nv_bfloat16 hi = __float2bfloat16(vv[q]);
                *(__nv_bfloat16*)(sm + SM_Z1H + rr * HPITCH_B + cc * 2) = hi;
                *(__nv_bfloat16*)(sm + SM_Z1L + rr * HPITCH_B + cc * 2) =
                    __float2bfloat16(vv[q] - __bfloat162float(hi));
            }
        }
    }
    __syncthreads();

    // ---- phase 2: agg = z1 @ rhoW1 + rhob1 (K=256)
    #pragma unroll
    for (int j = 0; j < 8; j++)
        #pragma unroll
        for (int q = 0; q < 4; q++) acc[j][q] = 0.f;

    for (int kt = 0; kt < 16; kt++) {
        uint4 Bv[8];
        #pragma unroll
        for (int j = 0; j < 8; j++)
            Bv[j] = __ldg(&g_r1i[kt * 1024 + ((wc * 8 + j) * 32 + lane)]);
        uint32_t ah[4], al[4];
        const uint32_t addr = smb + SM_Z1H
            + (uint32_t)(wr * 16 + (lane & 15)) * HPITCH_B
            + ((uint32_t)(lane >> 4)) * 16 + (uint32_t)kt * 32;
        ldmatrix4(ah, addr);
        ldmatrix4(al, addr + (SM_Z1L - SM_Z1H));
        #pragma unroll
        for (int j = 0; j < 8; j++) {
            mma16816(acc[j], ah, Bv[j].x, Bv[j].y);
            mma16816(acc[j], ah, Bv[j].z, Bv[j].w);
            mma16816(acc[j], al, Bv[j].x, Bv[j].y);
        }
    }
    {
        const int r0 = wr * 16 + (lane >> 2);
        #pragma unroll
        for (int j = 0; j < 8; j++) {
            const int c0 = wc * 64 + j * 8 + (lane & 3) * 2;
            const float b0v = __ldg(&rhob1[c0]), b1v = __ldg(&rhob1[c0 + 1]);
            float vv[4] = {acc[j][0] + b0v, acc[j][1] + b1v,
                           acc[j][2] + b0v, acc[j][3] + b1v};
            #pragma unroll
            for (int q = 0; q < 4; q++) {
                const int rr = (q < 2) ? r0 : r0 + 8;
                const int cc = c0 + (q & 1);
                __nv_bfloat16 hi = __float2bfloat16(vv[q]);
                *(__nv_bfloat16*)(sm + SM_XH + rr * HPITCH_B + cc * 2) = hi;
                *(__nv_bfloat16*)(sm + SM_XL + rr * HPITCH_B + cc * 2) =
                    __float2bfloat16(vv[q] - __bfloat162float(hi));
            }
        }
    }
    __syncthreads();

    // ---- phase 3: per-type out heads
    const float ml = *max_logit;
    for (int t = 0; t < 3; t++) {
        if (tid < 32) logits_s[tid] = 0.f;
        __syncthreads();

        #pragma unroll
        for (int j = 0; j < 8; j++)
            #pragma unroll
            for (int q = 0; q < 4; q++) acc[j][q] = 0.f;

        for (int kt = 0; kt < 16; kt++) {
            const int g = t * 16 + kt;
            uint4 Bv[8];
            #pragma unroll
            for (int j = 0; j < 8; j++)
                Bv[j] = __ldg(&g_oWi[g * 1024 + ((wc * 8 + j) * 32 + lane)]);
            uint32_t ah[4], al[4];
            const uint32_t addr = smb + SM_XH
                + (uint32_t)(wr * 16 + (lane & 15)) * HPITCH_B
                + ((uint32_t)(lane >> 4)) * 16 + (uint32_t)kt * 32;
            ldmatrix4(ah, addr);
            ldmatrix4(al, addr + (SM_XL - SM_XH));
            #pragma unroll
            for (int j = 0; j < 8; j++) {
                mma16816(acc[j], ah, Bv[j].x, Bv[j].y);
                mma16816(acc[j], ah, Bv[j].z, Bv[j].w);
                mma16816(acc[j], al, Bv[j].x, Bv[j].y);
            }
        }

        float p0 = 0.f, p1 = 0.f;
        #pragma unroll
        for (int j = 0; j < 8; j++) {
            const int c0 = wc * 64 + j * 8 + (lane & 3) * 2;
            const float bb0 = __ldg(&outb1[t * H + c0]);
            const float bb1 = __ldg(&outb1[t * H + c0 + 1]);
            const float w20 = __ldg(&outW2[t * H + c0]);
            const float w21 = __ldg(&outW2[t * H + c0 + 1]);
            p0 += lrelu(acc[j][0] + bb0) * w20 + lrelu(acc[j][1] + bb1) * w21;
            p1 += lrelu(acc[j][2] + bb0) * w20 + lrelu(acc[j][3] + bb1) * w21;
        }
        p0 += __shfl_xor_sync(0xffffffffu, p0, 1);
        p0 += __shfl_xor_sync(0xffffffffu, p0, 2);
        p1 += __shfl_xor_sync(0xffffffffu, p1, 1);
        p1 += __shfl_xor_sync(0xffffffffu, p1, 2);
        if ((lane & 3) == 0) {
            const int r0 = wr * 16 + (lane >> 2);
            atomicAdd(&logits_s[r0], p0);
            atomicAdd(&logits_s[r0 + 8], p1);
        }
        __syncthreads();
        if (tid < 32) {
            const int v = v0 + tid;
            if (vtypes[v] == t) {
                float l = logits_s[tid] + outb2[t];
                const int ci = min(g_alt_cnt[v], MAX_ALT);
                l *= conf[ci];
                out[v] = ml * tanhf(l / ml);
            }
        }
        __syncthreads();
    }
}

// ---------------- launch ----------------
extern "C" void kernel_launch(void* const* d_in, const int* in_sizes, int n_in,
                              void* d_out, int out_size)
{
    const float* reads  = (const float*)d_in[0];
    const float* info   = (const float*)d_in[1];
    const int*   refseg = (const int*)  d_in[2];
    const int*   altseg = (const int*)  d_in[3];
    const int*   vtypes = (const int*)  d_in[4];
    const float* phiW0  = (const float*)d_in[5];
    const float* phib0  = (const float*)d_in[6];
    const float* phiW1  = (const float*)d_in[7];
    const float* phib1  = (const float*)d_in[8];
    const float* omW0   = (const float*)d_in[9];
    const float* omb0   = (const float*)d_in[10];
    const float* rhoW0  = (const float*)d_in[11];
    const float* rhob0  = (const float*)d_in[12];
    const float* rhoW1  = (const float*)d_in[13];
    const float* rhob1  = (const float*)d_in[14];
    const float* outW1  = (const float*)d_in[15];
    const float* outb1  = (const float*)d_in[16];
    const float* outW2  = (const float*)d_in[17];
    const float* outb2  = (const float*)d_in[18];
    const float* conf   = (const float*)d_in[19];
    const float* maxl   = (const float*)d_in[20];
    float* out = (float*)d_out;

    cudaFuncSetAttribute(phi_mma_kernel,  cudaFuncAttributeMaxDynamicSharedMemorySize, PHI_SMEM_TOTAL);
    cudaFuncSetAttribute(head_mma_kernel, cudaFuncAttributeMaxDynamicSharedMemorySize, HEAD_SMEM_TOTAL);

    prelude_kernel<<<8704, 256>>>(phiW1, rhoW0, rhoW1, outW1);
    phi_mma_kernel<<<(NREF + NALT) / TILE_R, 256, PHI_SMEM_TOTAL>>>(
        reads, refseg, altseg, phiW0, phib0, phib1);
    head_mma_kernel<<<V / 32, 256, HEAD_SMEM_TOTAL>>>(
        vtypes, info, omW0, omb0, rhob0, rhob1, outb1, outb2, outW2, conf, maxl, out);
}

// round 12
// speedup vs baseline: 1.4509x; 1.1228x over previous
#include <cuda_runtime.h>
#include <cuda_bf16.h>
#include <math.h>
#include <stdint.h>

#define V     8192
#define NREF  262144
#define NALT  131072
#define FREAD 11
#define FINFO 9
#define H     256
#define MAX_ALT 10

#define TILE_R 64

// ---------------- scratch ----------------
__device__ float g_ref_sums[V * H];
__device__ float g_alt_sums[V * H];
__device__ int   g_ref_cnt[V];
__device__ int   g_alt_cnt[V];
// weights, interleaved mma fragments: uint4 {hi_r0, hi_r1, lo_r0, lo_r1} per [kt][nt(32)][lane(32)]
__device__ __align__(16) uint4 g_W0i[1024];        // phi W0 (K=16 padded from 11)
__device__ __align__(16) uint4 g_W1i[16 * 1024];   // phi W1 (K=256)
__device__ __align__(16) uint4 g_r0i[48 * 1024];
__device__ __align__(16) uint4 g_r1i[16 * 1024];
__device__ __align__(16) uint4 g_oWi[48 * 1024];

// ---------------- helpers ----------------
__device__ __forceinline__ float lrelu(float x) { return x > 0.f ? x : 0.01f * x; }
__device__ __forceinline__ float sigmoidf_(float x) { return 1.f / (1.f + __expf(-x)); }

__device__ __forceinline__ uint32_t pack_bf16x2(__nv_bfloat16 lo16, __nv_bfloat16 hi16) {
    return ((uint32_t)__bfloat16_as_ushort(hi16) << 16) | (uint32_t)__bfloat16_as_ushort(lo16);
}

__device__ __forceinline__ void mma16816(float* c, const uint32_t* a, uint32_t b0, uint32_t b1) {
    asm volatile(
        "mma.sync.aligned.m16n8k16.row.col.f32.bf16.bf16.f32 "
        "{%0,%1,%2,%3}, {%4,%5,%6,%7}, {%8,%9}, {%0,%1,%2,%3};"
        : "+f"(c[0]), "+f"(c[1]), "+f"(c[2]), "+f"(c[3])
        : "r"(a[0]), "r"(a[1]), "r"(a[2]), "r"(a[3]), "r"(b0), "r"(b1));
}

__device__ __forceinline__ void ldmatrix4(uint32_t* r, uint32_t addr) {
    asm volatile("ldmatrix.sync.aligned.m8n8.x4.shared.b16 {%0,%1,%2,%3}, [%4];"
                 : "=r"(r[0]), "=r"(r[1]), "=r"(r[2]), "=r"(r[3]) : "r"(addr));
}

__device__ __forceinline__ void cpasync16(uint32_t dst_smem, const void* src) {
    asm volatile("cp.async.cg.shared.global [%0], [%1], 16;" :: "r"(dst_smem), "l"(src) : "memory");
}

// ---------------- kernel 0: fused zero + all weight conversions ----------------
// blocks [0,8192): zero ; [8192, 8708): fragment conversions (W0:4, W1:64, r0:192, r1:64, oW:192)
__global__ void prelude_kernel(const float* __restrict__ W0, const float* __restrict__ W1,
                               const float* __restrict__ r0, const float* __restrict__ r1,
                               const float* __restrict__ oW) {
    const int b = blockIdx.x;
    const int tid = threadIdx.x;
    if (b < 8192) {
        const int idx = b * 256 + tid;
        g_ref_sums[idx] = 0.f;
        g_alt_sums[idx] = 0.f;
        if (idx < V) { g_ref_cnt[idx] = 0; g_alt_cnt[idx] = 0; }
        return;
    }
    int cb = b - 8192;
    const float* W;
    uint4* dst;
    int kmax = 1 << 30;
    if (cb < 4)        { W = W0; dst = g_W0i; kmax = FREAD; }
    else if (cb < 68)  { W = W1; dst = g_W1i; cb -= 4; }
    else if (cb < 260) { W = r0; dst = g_r0i; cb -= 68; }
    else if (cb < 324) { W = r1; dst = g_r1i; cb -= 260; }
    else               { W = oW; dst = g_oWi; cb -= 324; }
    const int idx = cb * 256 + tid;
    const int lane = idx & 31;
    const int nt   = (idx >> 5) & 31;
    const int kt   = idx >> 10;
    const int n = nt * 8 + (lane >> 2);
    const int kbase = kt * 16 + (lane & 3) * 2;
    uint32_t hv[2], lv[2];
    #pragma unroll
    for (int r = 0; r < 2; r++) {
        const int k = kbase + 8 * r;
        const float w0 = (k     < kmax) ? W[k * 256 + n]       : 0.f;
        const float w1 = (k + 1 < kmax) ? W[(k + 1) * 256 + n] : 0.f;
        __nv_bfloat16 h0 = __float2bfloat16(w0), h1 = __float2bfloat16(w1);
        __nv_bfloat16 l0 = __float2bfloat16(w0 - __bfloat162float(h0));
        __nv_bfloat16 l1 = __float2bfloat16(w1 - __bfloat162float(h1));
        hv[r] = pack_bf16x2(h0, h1);
        lv[r] = pack_bf16x2(l0, l1);
    }
    dst[idx] = make_uint4(hv[0], hv[1], lv[0], lv[1]);
}

// ---------------- kernel 1: fused phi MLP (all-mma) + segment reduce ----------------
// stage1: h = lrelu(x@W0+b0) via 3-term split mma (K=16 padded).
// stage2: y = sigmoid(bf16(h)@(W1h+W1l)+b1), cp.async 2-kt double-buffered B.
// smem: h[64][528B] | B 2x32KB | x frags hi/lo [64][48B] | segs. ys (64x257 f32) overlays h+B.
#define HPITCH_B 528
#define XPITCH_B 48
#define SM_HS    0
#define SM_B     33792                     // 2 x 32768, ends 99328
#define SM_XF    99328                     // 3072
#define SM_XFL   102400                    // 3072, ends 105472
#define SM_SEGS  105472                    // 256
#define PHI_SMEM_TOTAL 105984
#define YPITCH 257

__global__ __launch_bounds__(256, 2) void phi_mma_kernel(
    const float* __restrict__ reads,
    const int* __restrict__ ref_seg, const int* __restrict__ alt_seg,
    const float* __restrict__ b0, const float* __restrict__ b1)
{
    extern __shared__ char sm[];
    const uint32_t smb = (uint32_t)__cvta_generic_to_shared(sm);
    int*   segs = (int*)(sm + SM_SEGS);
    float* ys   = (float*)sm;

    const int tid = threadIdx.x;
    const long base = (long)blockIdx.x * TILE_R;
    const bool is_alt = (base >= NREF);
    const int* seg_src = is_alt ? (alt_seg + (base - NREF)) : (ref_seg + base);

    // prefetch B pair 0 (kt 0,1) into buffer 0
    #pragma unroll
    for (int i = 0; i < 8; i++) {
        const int c = tid + 256 * i;                 // 0..2047 uint4
        cpasync16(smb + SM_B + c * 16, &g_W1i[c]);
    }
    asm volatile("cp.async.commit_group;" ::: "memory");

    // x -> bf16 hi/lo fragment rows (pitch 48B, k padded to 16 with zeros)
    if (tid < TILE_R) {
        const float* rp = reads + (base + tid) * FREAD;
        float v[16];
        #pragma unroll
        for (int k = 0; k < 16; k++) v[k] = (k < FREAD) ? rp[k] : 0.f;
        uint32_t hrow[8], lrow[8];
        #pragma unroll
        for (int q = 0; q < 8; q++) {
            __nv_bfloat16 h0 = __float2bfloat16(v[2 * q]);
            __nv_bfloat16 h1 = __float2bfloat16(v[2 * q + 1]);
            __nv_bfloat16 l0 = __float2bfloat16(v[2 * q]     - __bfloat162float(h0));
            __nv_bfloat16 l1 = __float2bfloat16(v[2 * q + 1] - __bfloat162float(h1));
            hrow[q] = pack_bf16x2(h0, h1);
            lrow[q] = pack_bf16x2(l0, l1);
        }
        uint32_t* xh = (uint32_t*)(sm + SM_XF  + tid * XPITCH_B);
        uint32_t* xl = (uint32_t*)(sm + SM_XFL + tid * XPITCH_B);
        #pragma unroll
        for (int q = 0; q < 8; q++) { xh[q] = hrow[q]; xl[q] = lrow[q]; }
        segs[tid] = seg_src[tid];
    }
    __syncthreads();

    if (tid < TILE_R) {
        int* cnt = is_alt ? g_alt_cnt : g_ref_cnt;
        atomicAdd(&cnt[segs[tid]], 1);
    }

    const int wid = tid >> 5, lane = tid & 31;
    const int wr = wid >> 2, wc = wid & 3;
    const int rowbase = wr * 32;

    // ---- stage 1: h = lrelu(x @ W0 + b0) via mma (3-term split), write bf16 h to smem
    {
        float hacc[2][8][4];
        #pragma unroll
        for (int mt = 0; mt < 2; mt++)
            #pragma unroll
            for (int j = 0; j < 8; j++)
                #pragma unroll
                for (int q = 0; q < 4; q++) hacc[mt][j][q] = 0.f;

        uint4 B0[8];
        #pragma unroll
        for (int j = 0; j < 8; j++)
            B0[j] = __ldg(&g_W0i[(wc * 8 + j) * 32 + lane]);

        uint32_t xh[2][4], xl[2][4];
        #pragma unroll
        for (int mt = 0; mt < 2; mt++) {
            const uint32_t addr = smb + SM_XF
                + (uint32_t)(rowbase + mt * 16 + (lane & 15)) * XPITCH_B
                + ((uint32_t)(lane >> 4)) * 16;
            ldmatrix4(xh[mt], addr);
            ldmatrix4(xl[mt], addr + (SM_XFL - SM_XF));
        }
        #pragma unroll
        for (int j = 0; j < 8; j++) {
            #pragma unroll
            for (int mt = 0; mt < 2; mt++) {
                mma16816(hacc[mt][j], xh[mt], B0[j].x, B0[j].y);
                mma16816(hacc[mt][j], xh[mt], B0[j].z, B0[j].w);
                mma16816(hacc[mt][j], xl[mt], B0[j].x, B0[j].y);
            }
        }
        // epilogue: bias + lrelu -> bf16 pairs into SM_HS
        #pragma unroll
        for (int j = 0; j < 8; j++) {
            const int c0 = wc * 64 + j * 8 + (lane & 3) * 2;
            const float f0 = __ldg(&b0[c0]), f1 = __ldg(&b0[c0 + 1]);
            #pragma unroll
            for (int mt = 0; mt < 2; mt++) {
                const int row = rowbase + mt * 16 + (lane >> 2);
                __nv_bfloat162 p0 = __floats2bfloat162_rn(
                    lrelu(hacc[mt][j][0] + f0), lrelu(hacc[mt][j][1] + f1));
                __nv_bfloat162 p1 = __floats2bfloat162_rn(
                    lrelu(hacc[mt][j][2] + f0), lrelu(hacc[mt][j][3] + f1));
                *(__nv_bfloat162*)(sm + SM_HS + row * HPITCH_B + c0 * 2)       = p0;
                *(__nv_bfloat162*)(sm + SM_HS + (row + 8) * HPITCH_B + c0 * 2) = p1;
            }
        }
    }
    __syncthreads();

    // ---- stage 2: D[64][256] = bf16(h) @ (W1h + W1l), 2-kt pipelined B
    float acc[2][8][4];
    #pragma unroll
    for (int mt = 0; mt < 2; mt++)
        #pragma unroll
        for (int j = 0; j < 8; j++)
            #pragma unroll
            for (int q = 0; q < 4; q++) acc[mt][j][q] = 0.f;

    for (int p = 0; p < 8; p++) {
        if (p < 7) {
            const int s = (p + 1) & 1;
            #pragma unroll
            for (int i = 0; i < 8; i++) {
                const int c = tid + 256 * i;
                cpasync16(smb + SM_B + s * 32768 + c * 16, &g_W1i[(2 * (p + 1)) * 1024 + c]);
            }
            asm volatile("cp.async.commit_group;" ::: "memory");
            asm volatile("cp.async.wait_group 1;" ::: "memory");
        } else {
            asm volatile("cp.async.wait_group 0;" ::: "memory");
        }
        __syncthreads();   // pair p data visible

        #pragma unroll
        for (int kk = 0; kk < 2; kk++) {
            const int kt = 2 * p + kk;
            uint32_t ah[2][4];
            #pragma unroll
            for (int mt = 0; mt < 2; mt++) {
                const uint32_t addr = smb + SM_HS
                    + (uint32_t)(rowbase + mt * 16 + (lane & 15)) * HPITCH_B
                    + ((uint32_t)(lane >> 4)) * 16 + (uint32_t)kt * 32;
                ldmatrix4(ah[mt], addr);
            }
            const uint4* bbuf = (const uint4*)(sm + SM_B + (p & 1) * 32768 + kk * 16384);
            uint4 Bv[8];
            #pragma unroll
            for (int j = 0; j < 8; j++)
                Bv[j] = bbuf[(wc * 8 + j) * 32 + lane];
            #pragma unroll
            for (int j = 0; j < 8; j++) {
                #pragma unroll
                for (int mt = 0; mt < 2; mt++) {
                    mma16816(acc[mt][j], ah[mt], Bv[j].x, Bv[j].y);
                    mma16816(acc[mt][j], ah[mt], Bv[j].z, Bv[j].w);
                }
            }
        }
        __syncthreads();   // all reads of buf[p&1] done before it is restaged
    }

    // epilogue: bias + sigmoid -> ys[64][257] (overlays h + B; both dead)
    {
        const int colb = wc * 64 + 2 * (lane & 3);
        float bias0[8], bias1[8];
        #pragma unroll
        for (int j = 0; j < 8; j++) {
            bias0[j] = __ldg(&b1[colb + j * 8]);
            bias1[j] = __ldg(&b1[colb + j * 8 + 1]);
        }
        #pragma unroll
        for (int mt = 0; mt < 2; mt++) {
            const int row = rowbase + mt * 16 + (lane >> 2);
            #pragma unroll
            for (int j = 0; j < 8; j++) {
                const int col = colb + j * 8;
                ys[row * YPITCH + col]           = sigmoidf_(acc[mt][j][0] + bias0[j]);
                ys[row * YPITCH + col + 1]       = sigmoidf_(acc[mt][j][1] + bias1[j]);
                ys[(row + 8) * YPITCH + col]     = sigmoidf_(acc[mt][j][2] + bias0[j]);
                ys[(row + 8) * YPITCH + col + 1] = sigmoidf_(acc[mt][j][3] + bias1[j]);
            }
        }
    }
    __syncthreads();

    // sorted-run segment reduction: thread = column
    {
        float* sums = is_alt ? g_alt_sums : g_ref_sums;
        const int c = tid;
        int cur = segs[0];
        float a = 0.f;
        #pragma unroll 4
        for (int r = 0; r < TILE_R; r++) {
            int s = segs[r];
            if (s != cur) { atomicAdd(&sums[cur * H + c], a); a = 0.f; cur = s; }
            a += ys[r * YPITCH + c];
        }
        atomicAdd(&sums[cur * H + c], a);
    }
}

// ---------------- kernel 2: rho MLP + per-type heads (X computed in-kernel) ----------------
#define SM_XH    0
#define SM_XL    16896
#define SM_Z1H   33792
#define SM_Z1L   50688
#define SM_LOG   67584
#define SM_OM    67712
#define SM_INFO  76928
#define SM_RCP   78080
#define HEAD_SMEM_TOTAL 78336

__global__ __launch_bounds__(256, 2) void head_mma_kernel(
    const int* __restrict__ vtypes,
    const float* __restrict__ info,
    const float* __restrict__ omW0,  const float* __restrict__ omb0,
    const float* __restrict__ rhob0, const float* __restrict__ rhob1,
    const float* __restrict__ outb1, const float* __restrict__ outb2,
    const float* __restrict__ outW2,
    const float* __restrict__ conf,  const float* __restrict__ max_logit,
    float* __restrict__ out)
{
    extern __shared__ char sm[];
    const uint32_t smb = (uint32_t)__cvta_generic_to_shared(sm);
    float* logits_s = (float*)(sm + SM_LOG);
    float* om_s     = (float*)(sm + SM_OM);
    float* info_s   = (float*)(sm + SM_INFO);
    float* rcp_s    = (float*)(sm + SM_RCP);

    const int tid = threadIdx.x;
    const int wid = tid >> 5, lane = tid & 31;
    const int wr = wid >> 2, wc = wid & 3;
    const int v0 = blockIdx.x * 32;

    for (int i = tid; i < FINFO * H; i += 256) om_s[i] = omW0[i];
    for (int i = tid; i < 32 * FINFO; i += 256) info_s[i] = info[v0 * FINFO + i];
    if (tid < 32) {
        rcp_s[tid]      = 1.0f / (float)max(g_ref_cnt[v0 + tid], 1);
        rcp_s[tid + 32] = 1.0f / (float)max(g_alt_cnt[v0 + tid], 1);
    }
    __syncthreads();

    float acc[8][4];

    // ---- phase 1: z1 = lrelu(X @ rhoW0 + rhob0), K = 768 in 3 chunks of 256
    #pragma unroll
    for (int j = 0; j < 8; j++)
        #pragma unroll
        for (int q = 0; q < 4; q++) acc[j][q] = 0.f;

    for (int kb = 0; kb < 3; kb++) {
        if (kb < 2) {
            const float* sums = kb ? g_alt_sums : g_ref_sums;
            const float* rr   = rcp_s + kb * 32;
            for (int i = tid; i < 32 * H; i += 256) {
                const int c = i & 255, r = i >> 8;
                const float val = __ldg(&sums[(size_t)(v0 + r) * H + c]) * rr[r];
                __nv_bfloat16 hi = __float2bfloat16(val);
                *(__nv_bfloat16*)(sm + SM_XH + r * HPITCH_B + c * 2) = hi;
                *(__nv_bfloat16*)(sm + SM_XL + r * HPITCH_B + c * 2) =
                    __float2bfloat16(val - __bfloat162float(hi));
            }
        } else {
            for (int i = tid; i < 32 * H; i += 256) {
                const int c = i & 255, r = i >> 8;
                float z = __ldg(&omb0[c]);
                #pragma unroll
                for (int k = 0; k < FINFO; k++)
                    z = fmaf(info_s[r * FINFO + k], om_s[k * H + c], z);
                const float val = sigmoidf_(z);
                __nv_bfloat16 hi = __float2bfloat16(val);
                *(__nv_bfloat16*)(sm + SM_XH + r * HPITCH_B + c * 2) = hi;
                *(__nv_bfloat16*)(sm + SM_XL + r * HPITCH_B + c * 2) =
                    __float2bfloat16(val - __bfloat162float(hi));
            }
        }
        __syncthreads();
        for (int kt = 0; kt < 16; kt++) {
            const int g = kb * 16 + kt;
            uint4 Bv[8];
            #pragma unroll
            for (int j = 0; j < 8; j++)
                Bv[j] = __ldg(&g_r0i[g * 1024 + ((wc * 8 + j) * 32 + lane)]);
            uint32_t ah[4], al[4];
            const uint32_t addr = smb + SM_XH
                + (uint32_t)(wr * 16 + (lane & 15)) * HPITCH_B
                + ((uint32_t)(lane >> 4)) * 16 + (uint32_t)kt * 32;
            ldmatrix4(ah, addr);
            ldmatrix4(al, addr + (SM_XL - SM_XH));
            #pragma unroll
            for (int j = 0; j < 8; j++) {
                mma16816(acc[j], ah, Bv[j].x, Bv[j].y);
                mma16816(acc[j], ah, Bv[j].z, Bv[j].w);
                mma16816(acc[j], al, Bv[j].x, Bv[j].y);
            }
        }
        __syncthreads();
    }
    {
        const int r0 = wr * 16 + (lane >> 2);
        #pragma unroll
        for (int j = 0; j < 8; j++) {
            const int c0 = wc * 64 + j * 8 + (lane & 3) * 2;
            const float b0v = __ldg(&rhob0[c0]), b1v = __ldg(&rhob0[c0 + 1]);
            float vv[4] = {lrelu(acc[j][0] + b0v), lrelu(acc[j][1] + b1v),
                           lrelu(acc[j][2] + b0v), lrelu(acc[j][3] + b1v)};
            #pragma unroll
            for (int q = 0; q < 4; q++) {
                const int rr = (q < 2) ? r0 : r0 + 8;
                const int cc = c0 + (q & 1);
                __nv_bfloat16 hi = __float2bfloat16(vv[q]);
                *(__nv_bfloat16*)(sm + SM_Z1H + rr * HPITCH_B + cc * 2) = hi;
                *(__nv_bfloat16*)(sm + SM_Z1L + rr * HPITCH_B + cc * 2) =
                    __float2bfloat16(vv[q] - __bfloat162float(hi));
            }
        }
    }
    __syncthreads();

    // ---- phase 2: agg = z1 @ rhoW1 + rhob1 (K=256)
    #pragma unroll
    for (int j = 0; j < 8; j++)
        #pragma unroll
        for (int q = 0; q < 4; q++) acc[j][q] = 0.f;

    for (int kt = 0; kt < 16; kt++) {
        uint4 Bv[8];
        #pragma unroll
        for (int j = 0; j < 8; j++)
            Bv[j] = __ldg(&g_r1i[kt * 1024 + ((wc * 8 + j) * 32 + lane)]);
        uint32_t ah[4], al[4];
        const uint32_t addr = smb + SM_Z1H
            + (uint32_t)(wr * 16 + (lane & 15)) * HPITCH_B
            + ((uint32_t)(lane >> 4)) * 16 + (uint32_t)kt * 32;
        ldmatrix4(ah, addr);
        ldmatrix4(al, addr + (SM_Z1L - SM_Z1H));
        #pragma unroll
        for (int j = 0; j < 8; j++) {
            mma16816(acc[j], ah, Bv[j].x, Bv[j].y);
            mma16816(acc[j], ah, Bv[j].z, Bv[j].w);
            mma16816(acc[j], al, Bv[j].x, Bv[j].y);
        }
    }
    {
        const int r0 = wr * 16 + (lane >> 2);
        #pragma unroll
        for (int j = 0; j < 8; j++) {
            const int c0 = wc * 64 + j * 8 + (lane & 3) * 2;
            const float b0v = __ldg(&rhob1[c0]), b1v = __ldg(&rhob1[c0 + 1]);
            float vv[4] = {acc[j][0] + b0v, acc[j][1] + b1v,
                           acc[j][2] + b0v, acc[j][3] + b1v};
            #pragma unroll
            for (int q = 0; q < 4; q++) {
                const int rr = (q < 2) ? r0 : r0 + 8;
                const int cc = c0 + (q & 1);
                __nv_bfloat16 hi = __float2bfloat16(vv[q]);
                *(__nv_bfloat16*)(sm + SM_XH + rr * HPITCH_B + cc * 2) = hi;
                *(__nv_bfloat16*)(sm + SM_XL + rr * HPITCH_B + cc * 2) =
                    __float2bfloat16(vv[q] - __bfloat162float(hi));
            }
        }
    }
    __syncthreads();

    // ---- phase 3: per-type out heads
    const float ml = *max_logit;
    for (int t = 0; t < 3; t++) {
        if (tid < 32) logits_s[tid] = 0.f;
        __syncthreads();

        #pragma unroll
        for (int j = 0; j < 8; j++)
            #pragma unroll
            for (int q = 0; q < 4; q++) acc[j][q] = 0.f;

        for (int kt = 0; kt < 16; kt++) {
            const int g = t * 16 + kt;
            uint4 Bv[8];
            #pragma unroll
            for (int j = 0; j < 8; j++)
                Bv[j] = __ldg(&g_oWi[g * 1024 + ((wc * 8 + j) * 32 + lane)]);
            uint32_t ah[4], al[4];
            const uint32_t addr = smb + SM_XH
                + (uint32_t)(wr * 16 + (lane & 15)) * HPITCH_B
                + ((uint32_t)(lane >> 4)) * 16 + (uint32_t)kt * 32;
            ldmatrix4(ah, addr);
            ldmatrix4(al, addr + (SM_XL - SM_XH));
            #pragma unroll
            for (int j = 0; j < 8; j++) {
                mma16816(acc[j], ah, Bv[j].x, Bv[j].y);
                mma16816(acc[j], ah, Bv[j].z, Bv[j].w);
                mma16816(acc[j], al, Bv[j].x, Bv[j].y);
            }
        }

        float p0 = 0.f, p1 = 0.f;
        #pragma unroll
        for (int j = 0; j < 8; j++) {
            const int c0 = wc * 64 + j * 8 + (lane & 3) * 2;
            const float bb0 = __ldg(&outb1[t * H + c0]);
            const float bb1 = __ldg(&outb1[t * H + c0 + 1]);
            const float w20 = __ldg(&outW2[t * H + c0]);
            const float w21 = __ldg(&outW2[t * H + c0 + 1]);
            p0 += lrelu(acc[j][0] + bb0) * w20 + lrelu(acc[j][1] + bb1) * w21;
            p1 += lrelu(acc[j][2] + bb0) * w20 + lrelu(acc[j][3] + bb1) * w21;
        }
        p0 += __shfl_xor_sync(0xffffffffu, p0, 1);
        p0 += __shfl_xor_sync(0xffffffffu, p0, 2);
        p1 += __shfl_xor_sync(0xffffffffu, p1, 1);
        p1 += __shfl_xor_sync(0xffffffffu, p1, 2);
        if ((lane & 3) == 0) {
            const int r0 = wr * 16 + (lane >> 2);
            atomicAdd(&logits_s[r0], p0);
            atomicAdd(&logits_s[r0 + 8], p1);
        }
        __syncthreads();
        if (tid < 32) {
            const int v = v0 + tid;
            if (vtypes[v] == t) {
                float l = logits_s[tid] + outb2[t];
                const int ci = min(g_alt_cnt[v], MAX_ALT);
                l *= conf[ci];
                out[v] = ml * tanhf(l / ml);
            }
        }
        __syncthreads();
    }
}

// ---------------- launch ----------------
extern "C" void kernel_launch(void* const* d_in, const int* in_sizes, int n_in,
                              void* d_out, int out_size)
{
    const float* reads  = (const float*)d_in[0];
    const float* info   = (const float*)d_in[1];
    const int*   refseg = (const int*)  d_in[2];
    const int*   altseg = (const int*)  d_in[3];
    const int*   vtypes = (const int*)  d_in[4];
    const float* phiW0  = (const float*)d_in[5];
    const float* phib0  = (const float*)d_in[6];
    const float* phiW1  = (const float*)d_in[7];
    const float* phib1  = (const float*)d_in[8];
    const float* omW0   = (const float*)d_in[9];
    const float* omb0   = (const float*)d_in[10];
    const float* rhoW0  = (const float*)d_in[11];
    const float* rhob0  = (const float*)d_in[12];
    const float* rhoW1  = (const float*)d_in[13];
    const float* rhob1  = (const float*)d_in[14];
    const float* outW1  = (const float*)d_in[15];
    const float* outb1  = (const float*)d_in[16];
    const float* outW2  = (const float*)d_in[17];
    const float* outb2  = (const float*)d_in[18];
    const float* conf   = (const float*)d_in[19];
    const float* maxl   = (const float*)d_in[20];
    float* out = (float*)d_out;

    cudaFuncSetAttribute(phi_mma_kernel,  cudaFuncAttributeMaxDynamicSharedMemorySize, PHI_SMEM_TOTAL);
    cudaFuncSetAttribute(head_mma_kernel, cudaFuncAttributeMaxDynamicSharedMemorySize, HEAD_SMEM_TOTAL);

    prelude_kernel<<<8708, 256>>>(phiW0, phiW1, rhoW0, rhoW1, outW1);
    phi_mma_kernel<<<(NREF + NALT) / TILE_R, 256, PHI_SMEM_TOTAL>>>(
        reads, refseg, altseg, phib0, phib1);
    head_mma_kernel<<<V / 32, 256, HEAD_SMEM_TOTAL>>>(
        vtypes, info, omW0, omb0, rhob0, rhob1, outb1, outb2, outW2, conf, maxl, out);
}